// round 8
// baseline (speedup 1.0000x reference)
#include <cuda_runtime.h>
#include <cuda_bf16.h>
#include <cstdint>
#include <stdint.h>
#include <math.h>

// ---------------------------------------------------------------------------
// Transformer encoder block. All matmul work on tensor cores (tf32 mma.sync).
// Single-barrier cp.async pipelines in GEMM and attention.
// B=4, S=2048, D=1024, H=16, d_k=64, FFN=4096
// ---------------------------------------------------------------------------

#define D_MODEL 1024
#define N_HEADS 16
#define D_K     64
#define D_FF    4096
#define SEQ     2048
#define BATCH   4
#define M_ROWS  (BATCH * SEQ)          // 8192

// Scratch (device globals; allocation in kernel_launch is forbidden)
__device__ float g_Q  [M_ROWS * D_MODEL];
__device__ float g_K  [M_ROWS * D_MODEL];
__device__ float g_V  [M_ROWS * D_MODEL];
__device__ float g_ctx[M_ROWS * D_MODEL];
__device__ float g_prj[M_ROWS * D_MODEL];
__device__ float g_h  [M_ROWS * D_MODEL];
__device__ float g_mid[(size_t)M_ROWS * D_FF];
__device__ float g_f  [M_ROWS * D_MODEL];

__device__ __forceinline__ void cp16(uint32_t s, const float* g) {
    asm volatile("cp.async.cg.shared.global [%0], [%1], 16;\n" :: "r"(s), "l"(g));
}
__device__ __forceinline__ void cp_commit() {
    asm volatile("cp.async.commit_group;\n" ::: "memory");
}
__device__ __forceinline__ void cp_wait_all() {
    asm volatile("cp.async.wait_group 0;\n" ::: "memory");
}

__device__ __forceinline__ void mma_tf32(
    float& c0, float& c1, float& c2, float& c3,
    uint32_t a0, uint32_t a1, uint32_t a2, uint32_t a3,
    uint32_t b0, uint32_t b1)
{
    asm volatile(
        "mma.sync.aligned.m16n8k8.row.col.f32.tf32.tf32.f32 "
        "{%0,%1,%2,%3}, {%4,%5,%6,%7}, {%8,%9}, {%0,%1,%2,%3};\n"
        : "+f"(c0), "+f"(c1), "+f"(c2), "+f"(c3)
        : "r"(a0), "r"(a1), "r"(a2), "r"(a3), "r"(b0), "r"(b1));
}

// ---------------------------------------------------------------------------
// TF32 GEMM core: C[M,N] = A[M,K] @ B[K,N] + bias (+ optional ReLU)
// BM=128, BN=128, BK=32, 256 threads (8 warps), warp tile 64x32.
// Single __syncthreads per k-tile; cp.async double-buffered.
// ---------------------------------------------------------------------------
#define AS_STRIDE 36
#define BS_STRIDE 136
#define AS_ELEMS  (128 * AS_STRIDE)
#define BS_ELEMS  (32  * BS_STRIDE)
#define GEMM_SMEM_BYTES ((2 * AS_ELEMS + 2 * BS_ELEMS) * 4)  // 71680

__device__ __forceinline__ void gemm_core(
    const float* __restrict__ A, const float* __restrict__ B,
    const float* __restrict__ bias, float* __restrict__ C,
    int N, int K, int relu, int bm, int bn, float* smem)
{
    float* Asb[2] = { smem, smem + AS_ELEMS };
    float* Bsb[2] = { smem + 2 * AS_ELEMS, smem + 2 * AS_ELEMS + BS_ELEMS };

    const int tid  = threadIdx.x;
    const int lane = tid & 31;
    const int warp = tid >> 5;
    const int wm   = (warp >> 2) * 64;
    const int wn   = (warp & 3) * 32;
    const int r    = lane >> 2;
    const int c    = lane & 3;

    const float* Ab = A + (size_t)bm * 128 * K;
    const float* Bb = B + (size_t)bn * 128;

    uint32_t asAddr[2], bsAddr[2];
    asAddr[0] = (uint32_t)__cvta_generic_to_shared(Asb[0]);
    asAddr[1] = (uint32_t)__cvta_generic_to_shared(Asb[1]);
    bsAddr[0] = (uint32_t)__cvta_generic_to_shared(Bsb[0]);
    bsAddr[1] = (uint32_t)__cvta_generic_to_shared(Bsb[1]);

    float acc[4][4][4];
    #pragma unroll
    for (int i = 0; i < 4; i++)
        #pragma unroll
        for (int j = 0; j < 4; j++)
            #pragma unroll
            for (int k = 0; k < 4; k++) acc[i][j][k] = 0.0f;

    const int KT = K / 32;

    auto issue = [&](int kk, int b) {
        #pragma unroll
        for (int i = 0; i < 4; i++) {
            int id = tid + i * 256;
            int ar = id >> 3, ac = (id & 7) * 4;
            cp16(asAddr[b] + (uint32_t)(ar * AS_STRIDE + ac) * 4,
                 Ab + (size_t)ar * K + kk + ac);
            int br = id >> 5, bc = (id & 31) * 4;
            cp16(bsAddr[b] + (uint32_t)(br * BS_STRIDE + bc) * 4,
                 Bb + (size_t)(kk + br) * N + bc);
        }
        cp_commit();
    };

    issue(0, 0);

    for (int kt = 0; kt < KT; kt++) {
        cp_wait_all();
        __syncthreads();
        if (kt + 1 < KT) issue((kt + 1) * 32, (kt + 1) & 1);

        const float* As = Asb[kt & 1];
        const float* Bs = Bsb[kt & 1];

        #pragma unroll
        for (int ks = 0; ks < 4; ks++) {
            const int k0 = ks * 8;
            uint32_t af[4][4], bf[4][2];
            #pragma unroll
            for (int ma = 0; ma < 4; ma++) {
                const float* ap = As + (wm + ma * 16 + r) * AS_STRIDE + k0 + c;
                af[ma][0] = __float_as_uint(ap[0]);
                af[ma][2] = __float_as_uint(ap[4]);
                af[ma][1] = __float_as_uint(ap[8 * AS_STRIDE]);
                af[ma][3] = __float_as_uint(ap[8 * AS_STRIDE + 4]);
            }
            #pragma unroll
            for (int na = 0; na < 4; na++) {
                const float* bp = Bs + (k0 + c) * BS_STRIDE + wn + na * 8 + r;
                bf[na][0] = __float_as_uint(bp[0]);
                bf[na][1] = __float_as_uint(bp[4 * BS_STRIDE]);
            }
            #pragma unroll
            for (int ma = 0; ma < 4; ma++)
                #pragma unroll
                for (int na = 0; na < 4; na++)
                    mma_tf32(acc[ma][na][0], acc[ma][na][1],
                             acc[ma][na][2], acc[ma][na][3],
                             af[ma][0], af[ma][1], af[ma][2], af[ma][3],
                             bf[na][0], bf[na][1]);
        }
    }

    #pragma unroll
    for (int ma = 0; ma < 4; ma++) {
        const int row0 = bm * 128 + wm + ma * 16 + r;
        #pragma unroll
        for (int na = 0; na < 4; na++) {
            const int col = bn * 128 + wn + na * 8 + 2 * c;
            const float bv0 = bias[col];
            const float bv1 = bias[col + 1];
            float v0 = acc[ma][na][0] + bv0;
            float v1 = acc[ma][na][1] + bv1;
            float v2 = acc[ma][na][2] + bv0;
            float v3 = acc[ma][na][3] + bv1;
            if (relu) {
                v0 = fmaxf(v0, 0.f); v1 = fmaxf(v1, 0.f);
                v2 = fmaxf(v2, 0.f); v3 = fmaxf(v3, 0.f);
            }
            *(float2*)(C + (size_t)row0 * N + col)       = make_float2(v0, v1);
            *(float2*)(C + (size_t)(row0 + 8) * N + col) = make_float2(v2, v3);
        }
    }
}

__global__ __launch_bounds__(256) void tf32_gemm_kernel(
    const float* __restrict__ A, const float* __restrict__ B,
    const float* __restrict__ bias, float* __restrict__ C,
    int N, int K, int relu)
{
    extern __shared__ float smem[];
    gemm_core(A, B, bias, C, N, K, relu, blockIdx.y, blockIdx.x, smem);
}

// Fused QKV: grid.x = 24; bn>>3 selects {Wq,Wk,Wv}.
__global__ __launch_bounds__(256) void qkv_gemm_kernel(
    const float* __restrict__ x,
    const float* __restrict__ Wq, const float* __restrict__ bq, float* __restrict__ Qo,
    const float* __restrict__ Wk, const float* __restrict__ bk, float* __restrict__ Ko,
    const float* __restrict__ Wv, const float* __restrict__ bv, float* __restrict__ Vo)
{
    extern __shared__ float smem[];
    const int sel = blockIdx.x >> 3;
    const int bn  = blockIdx.x & 7;
    const float* B    = (sel == 0) ? Wq : (sel == 1) ? Wk : Wv;
    const float* bias = (sel == 0) ? bq : (sel == 1) ? bk : bv;
    float*       C    = (sel == 0) ? Qo : (sel == 1) ? Ko : Vo;
    gemm_core(x, B, bias, C, D_MODEL, D_MODEL, 0, blockIdx.y, bn, smem);
}

// ---------------------------------------------------------------------------
// Flash attention on tensor cores (tf32 mma), cp.async double-buffered K/V.
// Block: 128 q-rows, 256 threads (8 warps x 16 rows). K/V tile: 64 keys.
// One __syncthreads per k-tile. P is warp-private (own 16-row stripe).
// Smem: Ks stride 68 (bank=4r+c), Vs stride 72 (bank=8c+r), Ps stride 68.
// ---------------------------------------------------------------------------
#define ATT_QT   128
#define ATT_KT   64
#define KS_STR   68
#define VS_STR   72
#define PS_STR   68
#define KS_ELEMS (ATT_KT * KS_STR)     // 4352
#define VS_ELEMS (ATT_KT * VS_STR)     // 4608
#define PS_ELEMS (ATT_QT * PS_STR)     // 8704
#define ATT_SMEM_BYTES ((2 * (KS_ELEMS + VS_ELEMS) + PS_ELEMS) * 4)  // 106496

__global__ __launch_bounds__(256, 2) void attn_mma_kernel(
    const float* __restrict__ Q, const float* __restrict__ K,
    const float* __restrict__ V, float* __restrict__ O)
{
    extern __shared__ float sm[];
    float* Ksb[2] = { sm, sm + KS_ELEMS };
    float* Vsb[2] = { sm + 2 * KS_ELEMS, sm + 2 * KS_ELEMS + VS_ELEMS };
    float* Ps     = sm + 2 * (KS_ELEMS + VS_ELEMS);

    const int b    = blockIdx.z;
    const int h    = blockIdx.y;
    const int qt   = blockIdx.x;
    const int tid  = threadIdx.x;
    const int lane = tid & 31;
    const int warp = tid >> 5;
    const int r    = lane >> 2;       // 0..7
    const int c    = lane & 3;        // 0..3
    const int wm   = warp * 16;

    const size_t qrow0 = (size_t)b * SEQ + (size_t)qt * ATT_QT;
    const float* Qb = Q + qrow0 * D_MODEL + h * D_K;
    const float* Kb = K + (size_t)b * SEQ * D_MODEL + h * D_K;
    const float* Vb = V + (size_t)b * SEQ * D_MODEL + h * D_K;

    uint32_t ksAddr[2], vsAddr[2];
    ksAddr[0] = (uint32_t)__cvta_generic_to_shared(Ksb[0]);
    ksAddr[1] = (uint32_t)__cvta_generic_to_shared(Ksb[1]);
    vsAddr[0] = (uint32_t)__cvta_generic_to_shared(Vsb[0]);
    vsAddr[1] = (uint32_t)__cvta_generic_to_shared(Vsb[1]);

    auto issue_kv = [&](int kt, int buf) {
        #pragma unroll
        for (int i = 0; i < 4; i++) {
            int id  = tid + i * 256;
            int row = id >> 4, c4 = (id & 15) * 4;
            const float* gk = Kb + (size_t)(kt * ATT_KT + row) * D_MODEL + c4;
            const float* gv = Vb + (size_t)(kt * ATT_KT + row) * D_MODEL + c4;
            cp16(ksAddr[buf] + (uint32_t)(row * KS_STR + c4) * 4, gk);
            cp16(vsAddr[buf] + (uint32_t)(row * VS_STR + c4) * 4, gv);
        }
        cp_commit();
    };

    // prefetch tile 0 while staging Q
    issue_kv(0, 0);

    // stage Q tile (128x64) into Ps, then load Q fragments to registers
    for (int t = tid; t < ATT_QT * 16; t += 256) {
        int row = t >> 4, c4 = (t & 15) * 4;
        *(float4*)&Ps[row * PS_STR + c4] =
            *(const float4*)(Qb + (size_t)row * D_MODEL + c4);
    }
    __syncthreads();

    float qf[8][4];
    #pragma unroll
    for (int kk = 0; kk < 8; kk++) {
        const float* q0 = Ps + (wm + r) * PS_STR + kk * 8 + c;
        const float* q1 = Ps + (wm + r + 8) * PS_STR + kk * 8 + c;
        qf[kk][0] = q0[0] * 0.125f;
        qf[kk][1] = q1[0] * 0.125f;
        qf[kk][2] = q0[4] * 0.125f;
        qf[kk][3] = q1[4] * 0.125f;
    }
    // qf reads are same-warp-ordered before this warp's P writes; no block sync needed

    float oacc[8][4];
    #pragma unroll
    for (int nt = 0; nt < 8; nt++)
        #pragma unroll
        for (int i = 0; i < 4; i++) oacc[nt][i] = 0.0f;

    float m0 = -1e30f, m1 = -1e30f, l0 = 0.0f, l1 = 0.0f;

    const int NT = SEQ / ATT_KT;
    for (int kt = 0; kt < NT; kt++) {
        cp_wait_all();
        __syncthreads();                 // tile kt visible; all warps past tile kt-1
        if (kt + 1 < NT) issue_kv(kt + 1, (kt + 1) & 1);

        const float* Ks = Ksb[kt & 1];
        const float* Vs = Vsb[kt & 1];

        // ---- S = (Q/8) @ K^T
        float sacc[8][4];
        #pragma unroll
        for (int nt = 0; nt < 8; nt++) {
            sacc[nt][0] = sacc[nt][1] = sacc[nt][2] = sacc[nt][3] = 0.0f;
            #pragma unroll
            for (int kk = 0; kk < 8; kk++) {
                const float* kp = Ks + (nt * 8 + r) * KS_STR + kk * 8 + c;
                uint32_t b0 = __float_as_uint(kp[0]);
                uint32_t b1 = __float_as_uint(kp[4]);
                mma_tf32(sacc[nt][0], sacc[nt][1], sacc[nt][2], sacc[nt][3],
                         __float_as_uint(qf[kk][0]), __float_as_uint(qf[kk][1]),
                         __float_as_uint(qf[kk][2]), __float_as_uint(qf[kk][3]),
                         b0, b1);
            }
        }

        // ---- online softmax (thread owns rows wm+r and wm+r+8)
        float tm0 = -1e30f, tm1 = -1e30f;
        #pragma unroll
        for (int nt = 0; nt < 8; nt++) {
            tm0 = fmaxf(tm0, fmaxf(sacc[nt][0], sacc[nt][1]));
            tm1 = fmaxf(tm1, fmaxf(sacc[nt][2], sacc[nt][3]));
        }
        tm0 = fmaxf(tm0, __shfl_xor_sync(0xffffffffu, tm0, 1));
        tm0 = fmaxf(tm0, __shfl_xor_sync(0xffffffffu, tm0, 2));
        tm1 = fmaxf(tm1, __shfl_xor_sync(0xffffffffu, tm1, 1));
        tm1 = fmaxf(tm1, __shfl_xor_sync(0xffffffffu, tm1, 2));

        const float mn0 = fmaxf(m0, tm0);
        const float mn1 = fmaxf(m1, tm1);
        const float fac0 = __expf(m0 - mn0);
        const float fac1 = __expf(m1 - mn1);
        m0 = mn0; m1 = mn1;

        float ts0 = 0.0f, ts1 = 0.0f;
        #pragma unroll
        for (int nt = 0; nt < 8; nt++) {
            float p0 = __expf(sacc[nt][0] - mn0);
            float p1 = __expf(sacc[nt][1] - mn0);
            float p2 = __expf(sacc[nt][2] - mn1);
            float p3 = __expf(sacc[nt][3] - mn1);
            ts0 += p0 + p1;
            ts1 += p2 + p3;
            const int col = nt * 8 + c * 2;
            Ps[(wm + r) * PS_STR + col]         = p0;
            Ps[(wm + r) * PS_STR + col + 1]     = p1;
            Ps[(wm + r + 8) * PS_STR + col]     = p2;
            Ps[(wm + r + 8) * PS_STR + col + 1] = p3;
        }
        ts0 += __shfl_xor_sync(0xffffffffu, ts0, 1);
        ts0 += __shfl_xor_sync(0xffffffffu, ts0, 2);
        ts1 += __shfl_xor_sync(0xffffffffu, ts1, 1);
        ts1 += __shfl_xor_sync(0xffffffffu, ts1, 2);
        l0 = l0 * fac0 + ts0;
        l1 = l1 * fac1 + ts1;

        #pragma unroll
        for (int nt = 0; nt < 8; nt++) {
            oacc[nt][0] *= fac0; oacc[nt][1] *= fac0;
            oacc[nt][2] *= fac1; oacc[nt][3] *= fac1;
        }

        __syncwarp();   // P stripe is warp-private

        // ---- O += P @ V
        #pragma unroll
        for (int kk = 0; kk < 8; kk++) {
            const float* pp0 = Ps + (wm + r) * PS_STR + kk * 8 + c;
            const float* pp1 = Ps + (wm + r + 8) * PS_STR + kk * 8 + c;
            uint32_t a0 = __float_as_uint(pp0[0]);
            uint32_t a1 = __float_as_uint(pp1[0]);
            uint32_t a2 = __float_as_uint(pp0[4]);
            uint32_t a3 = __float_as_uint(pp1[4]);
            #pragma unroll
            for (int nt = 0; nt < 8; nt++) {
                const float* vp = Vs + (kk * 8 + c) * VS_STR + nt * 8 + r;
                uint32_t b0 = __float_as_uint(vp[0]);
                uint32_t b1 = __float_as_uint(vp[4 * VS_STR]);
                mma_tf32(oacc[nt][0], oacc[nt][1], oacc[nt][2], oacc[nt][3],
                         a0, a1, a2, a3, b0, b1);
            }
        }
    }

    // ---- normalize and store
    const float inv0 = 1.0f / l0;
    const float inv1 = 1.0f / l1;
    float* Ob = O + qrow0 * D_MODEL + h * D_K;
    #pragma unroll
    for (int nt = 0; nt < 8; nt++) {
        const int col = nt * 8 + c * 2;
        *(float2*)(Ob + (size_t)(wm + r) * D_MODEL + col) =
            make_float2(oacc[nt][0] * inv0, oacc[nt][1] * inv0);
        *(float2*)(Ob + (size_t)(wm + r + 8) * D_MODEL + col) =
            make_float2(oacc[nt][2] * inv1, oacc[nt][3] * inv1);
    }
}

// ---------------------------------------------------------------------------
// Fused residual-add + LayerNorm: out = LN(a + b) * g + beta
// ---------------------------------------------------------------------------
__global__ __launch_bounds__(256) void add_ln_kernel(
    const float* __restrict__ a, const float* __restrict__ b,
    const float* __restrict__ g, const float* __restrict__ beta,
    float* __restrict__ out)
{
    const int row = blockIdx.x;
    const int tid = threadIdx.x;

    const float4 av = *(const float4*)(a + (size_t)row * D_MODEL + tid * 4);
    const float4 bv = *(const float4*)(b + (size_t)row * D_MODEL + tid * 4);
    float4 v;
    v.x = av.x + bv.x; v.y = av.y + bv.y; v.z = av.z + bv.z; v.w = av.w + bv.w;

    float s  = v.x + v.y + v.z + v.w;
    float sq = v.x * v.x + v.y * v.y + v.z * v.z + v.w * v.w;

    #pragma unroll
    for (int off = 16; off; off >>= 1) {
        s  += __shfl_xor_sync(0xffffffffu, s,  off);
        sq += __shfl_xor_sync(0xffffffffu, sq, off);
    }
    __shared__ float red_s[8], red_q[8];
    if ((tid & 31) == 0) { red_s[tid >> 5] = s; red_q[tid >> 5] = sq; }
    __syncthreads();
    __shared__ float smean, srstd;
    if (tid == 0) {
        float ts = 0.f, tq = 0.f;
        #pragma unroll
        for (int i = 0; i < 8; i++) { ts += red_s[i]; tq += red_q[i]; }
        float mean = ts * (1.0f / D_MODEL);
        float var  = tq * (1.0f / D_MODEL) - mean * mean;
        smean = mean;
        srstd = rsqrtf(var + 1e-5f);
    }
    __syncthreads();
    const float mean = smean, rstd = srstd;

    const float4 gv = *(const float4*)(g    + tid * 4);
    const float4 tv = *(const float4*)(beta + tid * 4);
    float4 o;
    o.x = (v.x - mean) * rstd * gv.x + tv.x;
    o.y = (v.y - mean) * rstd * gv.y + tv.y;
    o.z = (v.z - mean) * rstd * gv.z + tv.z;
    o.w = (v.w - mean) * rstd * gv.w + tv.w;
    *(float4*)(out + (size_t)row * D_MODEL + tid * 4) = o;
}

// ---------------------------------------------------------------------------
// Launch
// ---------------------------------------------------------------------------
extern "C" void kernel_launch(void* const* d_in, const int* in_sizes, int n_in,
                              void* d_out, int out_size)
{
    const float* x     = (const float*)d_in[0];
    const float* Wq    = (const float*)d_in[1];
    const float* bq    = (const float*)d_in[2];
    const float* Wk    = (const float*)d_in[3];
    const float* bk    = (const float*)d_in[4];
    const float* Wv    = (const float*)d_in[5];
    const float* bv    = (const float*)d_in[6];
    const float* Wo    = (const float*)d_in[7];
    const float* bo    = (const float*)d_in[8];
    const float* ln1_g = (const float*)d_in[9];
    const float* ln1_b = (const float*)d_in[10];
    const float* W1    = (const float*)d_in[11];
    const float* b1    = (const float*)d_in[12];
    const float* W2    = (const float*)d_in[13];
    const float* b2    = (const float*)d_in[14];
    const float* ln2_g = (const float*)d_in[15];
    const float* ln2_b = (const float*)d_in[16];
    float* out = (float*)d_out;

    float *pQ, *pK, *pV, *pCtx, *pPrj, *pH, *pMid, *pF;
    cudaGetSymbolAddress((void**)&pQ,   g_Q);
    cudaGetSymbolAddress((void**)&pK,   g_K);
    cudaGetSymbolAddress((void**)&pV,   g_V);
    cudaGetSymbolAddress((void**)&pCtx, g_ctx);
    cudaGetSymbolAddress((void**)&pPrj, g_prj);
    cudaGetSymbolAddress((void**)&pH,   g_h);
    cudaGetSymbolAddress((void**)&pMid, g_mid);
    cudaGetSymbolAddress((void**)&pF,   g_f);

    cudaFuncSetAttribute(tf32_gemm_kernel,
                         cudaFuncAttributeMaxDynamicSharedMemorySize,
                         GEMM_SMEM_BYTES);
    cudaFuncSetAttribute(qkv_gemm_kernel,
                         cudaFuncAttributeMaxDynamicSharedMemorySize,
                         GEMM_SMEM_BYTES);
    cudaFuncSetAttribute(attn_mma_kernel,
                         cudaFuncAttributeMaxDynamicSharedMemorySize,
                         ATT_SMEM_BYTES);

    dim3 blk(256);
    dim3 gQKV (3 * D_MODEL / 128, M_ROWS / 128);   // (24, 64)
    dim3 gProj(D_MODEL / 128, M_ROWS / 128);       // (8, 64)
    dim3 gFF1 (D_FF   / 128, M_ROWS / 128);        // (32, 64)
    dim3 gFF2 (D_MODEL / 128, M_ROWS / 128);
    dim3 gAttn(SEQ / ATT_QT, N_HEADS, BATCH);      // (16, 16, 4)

    // fused QKV projections
    qkv_gemm_kernel<<<gQKV, blk, GEMM_SMEM_BYTES>>>(
        x, Wq, bq, pQ, Wk, bk, pK, Wv, bv, pV);

    // attention (tensor-core, double-buffered)
    attn_mma_kernel<<<gAttn, blk, ATT_SMEM_BYTES>>>(pQ, pK, pV, pCtx);

    // output projection
    tf32_gemm_kernel<<<gProj, blk, GEMM_SMEM_BYTES>>>(pCtx, Wo, bo, pPrj, D_MODEL, D_MODEL, 0);

    // residual + LN1
    add_ln_kernel<<<M_ROWS, blk>>>(pPrj, x, ln1_g, ln1_b, pH);

    // FFN
    tf32_gemm_kernel<<<gFF1, blk, GEMM_SMEM_BYTES>>>(pH, W1, b1, pMid, D_FF, D_MODEL, 1);
    tf32_gemm_kernel<<<gFF2, blk, GEMM_SMEM_BYTES>>>(pMid, W2, b2, pF, D_MODEL, D_FF, 0);

    // residual + LN2 -> output
    add_ln_kernel<<<M_ROWS, blk>>>(pF, pH, ln2_g, ln2_b, out);
}

// round 9
// speedup vs baseline: 2.2968x; 2.2968x over previous
#include <cuda_runtime.h>
#include <cuda_bf16.h>
#include <cuda_fp16.h>
#include <cstdint>
#include <stdint.h>
#include <math.h>

// ---------------------------------------------------------------------------
// Transformer encoder block, fp16 tensor-core path (m16n8k16 mma, fp32 accum).
// fp16 mantissa == tf32 mantissa (10 bits) -> same precision, 2x throughput.
// B=4, S=2048, D=1024, H=16, d_k=64, FFN=4096
// ---------------------------------------------------------------------------

#define D_MODEL 1024
#define N_HEADS 16
#define D_K     64
#define D_FF    4096
#define SEQ     2048
#define BATCH   4
#define M_ROWS  (BATCH * SEQ)          // 8192

// fp32 scratch
__device__ float g_prj[M_ROWS * D_MODEL];
__device__ float g_h  [M_ROWS * D_MODEL];
__device__ float g_f  [M_ROWS * D_MODEL];
// fp16 scratch
__device__ __half g_x16 [M_ROWS * D_MODEL];
__device__ __half g_Wq16[D_MODEL * D_MODEL];
__device__ __half g_Wk16[D_MODEL * D_MODEL];
__device__ __half g_Wv16[D_MODEL * D_MODEL];
__device__ __half g_Wo16[D_MODEL * D_MODEL];
__device__ __half g_W116[D_MODEL * D_FF];
__device__ __half g_W216[D_FF * D_MODEL];
__device__ __half g_Q16 [M_ROWS * D_MODEL];
__device__ __half g_K16 [M_ROWS * D_MODEL];
__device__ __half g_V16 [M_ROWS * D_MODEL];
__device__ __half g_ctx [M_ROWS * D_MODEL];
__device__ __half g_h16 [M_ROWS * D_MODEL];
__device__ __half g_mid [(size_t)M_ROWS * D_FF];

// ---------------------------------------------------------------------------
// primitives
// ---------------------------------------------------------------------------
__device__ __forceinline__ void cp16(uint32_t s, const void* g) {
    asm volatile("cp.async.cg.shared.global [%0], [%1], 16;\n" :: "r"(s), "l"(g));
}
__device__ __forceinline__ void cp_commit() {
    asm volatile("cp.async.commit_group;\n" ::: "memory");
}

__device__ __forceinline__ void mma_f16(
    float& c0, float& c1, float& c2, float& c3,
    uint32_t a0, uint32_t a1, uint32_t a2, uint32_t a3,
    uint32_t b0, uint32_t b1)
{
    asm volatile(
        "mma.sync.aligned.m16n8k16.row.col.f32.f16.f16.f32 "
        "{%0,%1,%2,%3}, {%4,%5,%6,%7}, {%8,%9}, {%0,%1,%2,%3};\n"
        : "+f"(c0), "+f"(c1), "+f"(c2), "+f"(c3)
        : "r"(a0), "r"(a1), "r"(a2), "r"(a3), "r"(b0), "r"(b1));
}

__device__ __forceinline__ void ldsm_x4(uint32_t& r0, uint32_t& r1,
                                        uint32_t& r2, uint32_t& r3, uint32_t a) {
    asm volatile("ldmatrix.sync.aligned.m8n8.x4.shared.b16 {%0,%1,%2,%3}, [%4];"
                 : "=r"(r0), "=r"(r1), "=r"(r2), "=r"(r3) : "r"(a));
}
__device__ __forceinline__ void ldsm_x2(uint32_t& r0, uint32_t& r1, uint32_t a) {
    asm volatile("ldmatrix.sync.aligned.m8n8.x2.shared.b16 {%0,%1}, [%2];"
                 : "=r"(r0), "=r"(r1) : "r"(a));
}
__device__ __forceinline__ void ldsm_x2_t(uint32_t& r0, uint32_t& r1, uint32_t a) {
    asm volatile("ldmatrix.sync.aligned.m8n8.x2.trans.shared.b16 {%0,%1}, [%2];"
                 : "=r"(r0), "=r"(r1) : "r"(a));
}

// ---------------------------------------------------------------------------
// fp32 -> fp16 conversion (weights + x), once per launch
// ---------------------------------------------------------------------------
__global__ __launch_bounds__(256) void cvt16_kernel(
    const float* __restrict__ s, __half* __restrict__ d, int n)
{
    int i = (blockIdx.x * 256 + threadIdx.x) * 4;
    if (i < n) {
        float4 v = *(const float4*)(s + i);
        *(__half2*)(d + i)     = __floats2half2_rn(v.x, v.y);
        *(__half2*)(d + i + 2) = __floats2half2_rn(v.z, v.w);
    }
}

// ---------------------------------------------------------------------------
// FP16 GEMM: C[M,N] = A[M,K] @ B[K,N] + bias (+ReLU) (C fp32 or fp16)
// BM=128, BN=128, BK=32, 256 threads (8 warps), warp tile 64x32,
// mma m16n8k16, ldmatrix fragments, cp.async double-buffered.
// Smem strides (halfs): A 40 (80B=20 words -> 4i bank pattern),
//                       B 136 (272B=68 words -> 4i bank pattern).
// ---------------------------------------------------------------------------
#define A_STR 40
#define B_STR 136
#define A_ELE (128 * A_STR)   // 5120 halfs
#define B_ELE (32  * B_STR)   // 4352 halfs

__global__ __launch_bounds__(256) void gemm_f16_kernel(
    const __half* __restrict__ A, const __half* __restrict__ B,
    const float* __restrict__ bias, void* __restrict__ Cout,
    int N, int K, int relu, int half_out)
{
    __shared__ __half Asb[2][A_ELE];
    __shared__ __half Bsb[2][B_ELE];

    const int tid  = threadIdx.x;
    const int lane = tid & 31;
    const int warp = tid >> 5;
    const int wm   = (warp >> 2) * 64;
    const int wn   = (warp & 3) * 32;
    const int r    = lane >> 2;
    const int c    = lane & 3;
    const int bm   = blockIdx.y;
    const int bn   = blockIdx.x;

    const __half* Ab = A + (size_t)bm * 128 * K;
    const __half* Bb = B + (size_t)bn * 128;

    uint32_t asAddr[2], bsAddr[2];
    asAddr[0] = (uint32_t)__cvta_generic_to_shared(Asb[0]);
    asAddr[1] = (uint32_t)__cvta_generic_to_shared(Asb[1]);
    bsAddr[0] = (uint32_t)__cvta_generic_to_shared(Bsb[0]);
    bsAddr[1] = (uint32_t)__cvta_generic_to_shared(Bsb[1]);

    float acc[4][4][4];
    #pragma unroll
    for (int i = 0; i < 4; i++)
        #pragma unroll
        for (int j = 0; j < 4; j++)
            #pragma unroll
            for (int k = 0; k < 4; k++) acc[i][j][k] = 0.0f;

    const int KT = K / 32;

    auto issue = [&](int kk, int b) {
        #pragma unroll
        for (int i = 0; i < 2; i++) {
            int id = tid + i * 256;
            int ar = id >> 2, ac = (id & 3) * 8;            // A: 128 rows x 4 chunks
            cp16(asAddr[b] + (uint32_t)(ar * A_STR + ac) * 2,
                 Ab + (size_t)ar * K + kk + ac);
            int br = id >> 4, bc = (id & 15) * 8;           // B: 32 rows x 16 chunks
            cp16(bsAddr[b] + (uint32_t)(br * B_STR + bc) * 2,
                 Bb + (size_t)(kk + br) * N + bc);
        }
        cp_commit();
    };

    issue(0, 0);
    int buf = 0;

    const int lrow = lane & 15;
    const int lcol = (lane & 16) ? 8 : 0;

    for (int kt = 0; kt < KT; kt++) {
        if (kt + 1 < KT) {
            issue((kt + 1) * 32, buf ^ 1);
            asm volatile("cp.async.wait_group 1;\n" ::: "memory");
        } else {
            asm volatile("cp.async.wait_group 0;\n" ::: "memory");
        }
        __syncthreads();

        #pragma unroll
        for (int ks = 0; ks < 2; ks++) {
            const int k0 = ks * 16;
            uint32_t af[4][4], bf[4][2];
            #pragma unroll
            for (int ma = 0; ma < 4; ma++) {
                uint32_t a = asAddr[buf] +
                    (uint32_t)((wm + ma * 16 + lrow) * A_STR + k0 + lcol) * 2;
                ldsm_x4(af[ma][0], af[ma][1], af[ma][2], af[ma][3], a);
            }
            #pragma unroll
            for (int na = 0; na < 4; na++) {
                uint32_t a = bsAddr[buf] +
                    (uint32_t)((k0 + lrow) * B_STR + wn + na * 8) * 2;
                ldsm_x2_t(bf[na][0], bf[na][1], a);
            }
            #pragma unroll
            for (int ma = 0; ma < 4; ma++)
                #pragma unroll
                for (int na = 0; na < 4; na++)
                    mma_f16(acc[ma][na][0], acc[ma][na][1],
                            acc[ma][na][2], acc[ma][na][3],
                            af[ma][0], af[ma][1], af[ma][2], af[ma][3],
                            bf[na][0], bf[na][1]);
        }
        __syncthreads();
        buf ^= 1;
    }

    // epilogue
    #pragma unroll
    for (int ma = 0; ma < 4; ma++) {
        const int row0 = bm * 128 + wm + ma * 16 + r;
        #pragma unroll
        for (int na = 0; na < 4; na++) {
            const int col = bn * 128 + wn + na * 8 + 2 * c;
            const float bv0 = bias[col];
            const float bv1 = bias[col + 1];
            float v0 = acc[ma][na][0] + bv0;
            float v1 = acc[ma][na][1] + bv1;
            float v2 = acc[ma][na][2] + bv0;
            float v3 = acc[ma][na][3] + bv1;
            if (relu) {
                v0 = fmaxf(v0, 0.f); v1 = fmaxf(v1, 0.f);
                v2 = fmaxf(v2, 0.f); v3 = fmaxf(v3, 0.f);
            }
            if (half_out) {
                __half* C = (__half*)Cout;
                *(__half2*)(C + (size_t)row0 * N + col)       = __floats2half2_rn(v0, v1);
                *(__half2*)(C + (size_t)(row0 + 8) * N + col) = __floats2half2_rn(v2, v3);
            } else {
                float* C = (float*)Cout;
                *(float2*)(C + (size_t)row0 * N + col)       = make_float2(v0, v1);
                *(float2*)(C + (size_t)(row0 + 8) * N + col) = make_float2(v2, v3);
            }
        }
    }
}

// ---------------------------------------------------------------------------
// Flash attention, fp16 mma (m16n8k16), fp32 accum + softmax.
// Block: 128 q-rows, 256 threads (8 warps x 16 rows). K/V tile: 64 keys.
// Smem (halfs, stride 72 = 144B = 36 words -> 4i bank pattern):
//   Ks[64][72], Vs[64][72], Ps[128][72] (Q staging, then P)
// ---------------------------------------------------------------------------
#define ATT_QT  128
#define ATT_KT  64
#define AKS_STR 72

__global__ __launch_bounds__(256) void attn_f16_kernel(
    const __half* __restrict__ Q, const __half* __restrict__ K,
    const __half* __restrict__ V, __half* __restrict__ O)
{
    __shared__ __half Ks[ATT_KT * AKS_STR];
    __shared__ __half Vs[ATT_KT * AKS_STR];
    __shared__ __half Ps[ATT_QT * AKS_STR];

    const int b    = blockIdx.z;
    const int h    = blockIdx.y;
    const int qt   = blockIdx.x;
    const int tid  = threadIdx.x;
    const int lane = tid & 31;
    const int warp = tid >> 5;
    const int r    = lane >> 2;       // 0..7
    const int c    = lane & 3;        // 0..3
    const int wm   = warp * 16;
    const int lrow = lane & 15;
    const int lcol = (lane & 16) ? 8 : 0;

    const size_t qrow0 = (size_t)b * SEQ + (size_t)qt * ATT_QT;
    const __half* Qb = Q + qrow0 * D_MODEL + h * D_K;
    const __half* Kb = K + (size_t)b * SEQ * D_MODEL + h * D_K;
    const __half* Vb = V + (size_t)b * SEQ * D_MODEL + h * D_K;

    const uint32_t ksB = (uint32_t)__cvta_generic_to_shared(Ks);
    const uint32_t vsB = (uint32_t)__cvta_generic_to_shared(Vs);
    const uint32_t psB = (uint32_t)__cvta_generic_to_shared(Ps);

    // ---- stage Q tile (128 x 64 halfs) into Ps, load Q fragments to regs
    #pragma unroll
    for (int i = 0; i < 4; i++) {
        int id = tid + i * 256;                 // 1024 chunks of 8 halfs
        int row = id >> 3, c8 = (id & 7) * 8;
        *(uint4*)&Ps[row * AKS_STR + c8] =
            *(const uint4*)(Qb + (size_t)row * D_MODEL + c8);
    }
    __syncthreads();

    uint32_t qa[4][4];
    #pragma unroll
    for (int ks = 0; ks < 4; ks++) {
        uint32_t a = psB + (uint32_t)((wm + lrow) * AKS_STR + ks * 16 + lcol) * 2;
        ldsm_x4(qa[ks][0], qa[ks][1], qa[ks][2], qa[ks][3], a);
    }
    __syncthreads();   // Ps reused for P below

    float oacc[8][4];
    #pragma unroll
    for (int nt = 0; nt < 8; nt++)
        #pragma unroll
        for (int i = 0; i < 4; i++) oacc[nt][i] = 0.0f;

    float m0 = -1e30f, m1 = -1e30f, l0 = 0.0f, l1 = 0.0f;

    for (int kt = 0; kt < SEQ / ATT_KT; kt++) {
        // ---- load K,V tiles (64 x 64 halfs each)
        #pragma unroll
        for (int i = 0; i < 2; i++) {
            int id = tid + i * 256;             // 512 chunks each
            int row = id >> 3, c8 = (id & 7) * 8;
            const size_t gro = (size_t)(kt * ATT_KT + row) * D_MODEL + c8;
            *(uint4*)&Ks[row * AKS_STR + c8] = *(const uint4*)(Kb + gro);
            *(uint4*)&Vs[row * AKS_STR + c8] = *(const uint4*)(Vb + gro);
        }
        __syncthreads();

        // ---- S = Q @ K^T  (B-frag from Ks[key][d] via non-trans ldmatrix.x2)
        float sacc[8][4];
        #pragma unroll
        for (int nt = 0; nt < 8; nt++) {
            sacc[nt][0] = sacc[nt][1] = sacc[nt][2] = sacc[nt][3] = 0.0f;
            #pragma unroll
            for (int ks = 0; ks < 4; ks++) {
                uint32_t addr = ksB + (uint32_t)(
                    (nt * 8 + (lane & 7)) * AKS_STR + ks * 16 + ((lane & 8) ? 8 : 0)) * 2;
                uint32_t b0, b1;
                ldsm_x2(b0, b1, addr);
                mma_f16(sacc[nt][0], sacc[nt][1], sacc[nt][2], sacc[nt][3],
                        qa[ks][0], qa[ks][1], qa[ks][2], qa[ks][3], b0, b1);
            }
            sacc[nt][0] *= 0.125f; sacc[nt][1] *= 0.125f;
            sacc[nt][2] *= 0.125f; sacc[nt][3] *= 0.125f;
        }

        // ---- online softmax (thread owns rows wm+r, wm+r+8)
        float tm0 = -1e30f, tm1 = -1e30f;
        #pragma unroll
        for (int nt = 0; nt < 8; nt++) {
            tm0 = fmaxf(tm0, fmaxf(sacc[nt][0], sacc[nt][1]));
            tm1 = fmaxf(tm1, fmaxf(sacc[nt][2], sacc[nt][3]));
        }
        tm0 = fmaxf(tm0, __shfl_xor_sync(0xffffffffu, tm0, 1));
        tm0 = fmaxf(tm0, __shfl_xor_sync(0xffffffffu, tm0, 2));
        tm1 = fmaxf(tm1, __shfl_xor_sync(0xffffffffu, tm1, 1));
        tm1 = fmaxf(tm1, __shfl_xor_sync(0xffffffffu, tm1, 2));

        const float mn0 = fmaxf(m0, tm0);
        const float mn1 = fmaxf(m1, tm1);
        const float fac0 = __expf(m0 - mn0);
        const float fac1 = __expf(m1 - mn1);
        m0 = mn0; m1 = mn1;

        float ts0 = 0.0f, ts1 = 0.0f;
        #pragma unroll
        for (int nt = 0; nt < 8; nt++) {
            float p0 = __expf(sacc[nt][0] - mn0);
            float p1 = __expf(sacc[nt][1] - mn0);
            float p2 = __expf(sacc[nt][2] - mn1);
            float p3 = __expf(sacc[nt][3] - mn1);
            ts0 += p0 + p1;
            ts1 += p2 + p3;
            const int col = nt * 8 + c * 2;
            *(__half2*)&Ps[(wm + r) * AKS_STR + col]     = __floats2half2_rn(p0, p1);
            *(__half2*)&Ps[(wm + r + 8) * AKS_STR + col] = __floats2half2_rn(p2, p3);
        }
        ts0 += __shfl_xor_sync(0xffffffffu, ts0, 1);
        ts0 += __shfl_xor_sync(0xffffffffu, ts0, 2);
        ts1 += __shfl_xor_sync(0xffffffffu, ts1, 1);
        ts1 += __shfl_xor_sync(0xffffffffu, ts1, 2);
        l0 = l0 * fac0 + ts0;
        l1 = l1 * fac1 + ts1;

        #pragma unroll
        for (int nt = 0; nt < 8; nt++) {
            oacc[nt][0] *= fac0; oacc[nt][1] *= fac0;
            oacc[nt][2] *= fac1; oacc[nt][3] *= fac1;
        }

        __syncwarp();   // P stripe is warp-private

        // ---- O += P @ V  (A from Ps via ldmatrix.x4; B from Vs via x2.trans)
        #pragma unroll
        for (int ks = 0; ks < 4; ks++) {
            const int k0 = ks * 16;
            uint32_t a0, a1, a2, a3;
            ldsm_x4(a0, a1, a2, a3,
                    psB + (uint32_t)((wm + lrow) * AKS_STR + k0 + lcol) * 2);
            #pragma unroll
            for (int nt = 0; nt < 8; nt++) {
                uint32_t b0, b1;
                ldsm_x2_t(b0, b1,
                          vsB + (uint32_t)((k0 + lrow) * AKS_STR + nt * 8) * 2);
                mma_f16(oacc[nt][0], oacc[nt][1], oacc[nt][2], oacc[nt][3],
                        a0, a1, a2, a3, b0, b1);
            }
        }
        __syncthreads();   // protect Ks/Vs/Ps before next tile
    }

    // ---- normalize and store (fp16 ctx)
    const float inv0 = 1.0f / l0;
    const float inv1 = 1.0f / l1;
    __half* Ob = O + qrow0 * D_MODEL + h * D_K;
    #pragma unroll
    for (int nt = 0; nt < 8; nt++) {
        const int col = nt * 8 + c * 2;
        *(__half2*)(Ob + (size_t)(wm + r) * D_MODEL + col) =
            __floats2half2_rn(oacc[nt][0] * inv0, oacc[nt][1] * inv0);
        *(__half2*)(Ob + (size_t)(wm + r + 8) * D_MODEL + col) =
            __floats2half2_rn(oacc[nt][2] * inv1, oacc[nt][3] * inv1);
    }
}

// ---------------------------------------------------------------------------
// Fused residual-add + LayerNorm: out = LN(a + b) * g + beta
// Optionally also emits fp16 copy (for feeding next GEMM).
// ---------------------------------------------------------------------------
__global__ __launch_bounds__(256) void add_ln_kernel(
    const float* __restrict__ a, const float* __restrict__ b,
    const float* __restrict__ g, const float* __restrict__ beta,
    float* __restrict__ out, __half* __restrict__ out16, int w16)
{
    const int row = blockIdx.x;
    const int tid = threadIdx.x;

    const float4 av = *(const float4*)(a + (size_t)row * D_MODEL + tid * 4);
    const float4 bv = *(const float4*)(b + (size_t)row * D_MODEL + tid * 4);
    float4 v;
    v.x = av.x + bv.x; v.y = av.y + bv.y; v.z = av.z + bv.z; v.w = av.w + bv.w;

    float s  = v.x + v.y + v.z + v.w;
    float sq = v.x * v.x + v.y * v.y + v.z * v.z + v.w * v.w;

    #pragma unroll
    for (int off = 16; off; off >>= 1) {
        s  += __shfl_xor_sync(0xffffffffu, s,  off);
        sq += __shfl_xor_sync(0xffffffffu, sq, off);
    }
    __shared__ float red_s[8], red_q[8];
    if ((tid & 31) == 0) { red_s[tid >> 5] = s; red_q[tid >> 5] = sq; }
    __syncthreads();
    __shared__ float smean, srstd;
    if (tid == 0) {
        float ts = 0.f, tq = 0.f;
        #pragma unroll
        for (int i = 0; i < 8; i++) { ts += red_s[i]; tq += red_q[i]; }
        float mean = ts * (1.0f / D_MODEL);
        float var  = tq * (1.0f / D_MODEL) - mean * mean;
        smean = mean;
        srstd = rsqrtf(var + 1e-5f);
    }
    __syncthreads();
    const float mean = smean, rstd = srstd;

    const float4 gv = *(const float4*)(g    + tid * 4);
    const float4 tv = *(const float4*)(beta + tid * 4);
    float4 o;
    o.x = (v.x - mean) * rstd * gv.x + tv.x;
    o.y = (v.y - mean) * rstd * gv.y + tv.y;
    o.z = (v.z - mean) * rstd * gv.z + tv.z;
    o.w = (v.w - mean) * rstd * gv.w + tv.w;
    *(float4*)(out + (size_t)row * D_MODEL + tid * 4) = o;
    if (w16) {
        __half2 h0 = __floats2half2_rn(o.x, o.y);
        __half2 h1 = __floats2half2_rn(o.z, o.w);
        *(__half2*)(out16 + (size_t)row * D_MODEL + tid * 4)     = h0;
        *(__half2*)(out16 + (size_t)row * D_MODEL + tid * 4 + 2) = h1;
    }
}

// ---------------------------------------------------------------------------
// Launch
// ---------------------------------------------------------------------------
extern "C" void kernel_launch(void* const* d_in, const int* in_sizes, int n_in,
                              void* d_out, int out_size)
{
    const float* x     = (const float*)d_in[0];
    const float* Wq    = (const float*)d_in[1];
    const float* bq    = (const float*)d_in[2];
    const float* Wk    = (const float*)d_in[3];
    const float* bk    = (const float*)d_in[4];
    const float* Wv    = (const float*)d_in[5];
    const float* bv    = (const float*)d_in[6];
    const float* Wo    = (const float*)d_in[7];
    const float* bo    = (const float*)d_in[8];
    const float* ln1_g = (const float*)d_in[9];
    const float* ln1_b = (const float*)d_in[10];
    const float* W1    = (const float*)d_in[11];
    const float* b1    = (const float*)d_in[12];
    const float* W2    = (const float*)d_in[13];
    const float* b2    = (const float*)d_in[14];
    const float* ln2_g = (const float*)d_in[15];
    const float* ln2_b = (const float*)d_in[16];
    float* out = (float*)d_out;

    float *pPrj, *pH, *pF;
    __half *pX16, *pWq, *pWk, *pWv, *pWo, *pW1, *pW2;
    __half *pQ, *pK, *pV, *pCtx, *pH16, *pMid;
    cudaGetSymbolAddress((void**)&pPrj, g_prj);
    cudaGetSymbolAddress((void**)&pH,   g_h);
    cudaGetSymbolAddress((void**)&pF,   g_f);
    cudaGetSymbolAddress((void**)&pX16, g_x16);
    cudaGetSymbolAddress((void**)&pWq,  g_Wq16);
    cudaGetSymbolAddress((void**)&pWk,  g_Wk16);
    cudaGetSymbolAddress((void**)&pWv,  g_Wv16);
    cudaGetSymbolAddress((void**)&pWo,  g_Wo16);
    cudaGetSymbolAddress((void**)&pW1,  g_W116);
    cudaGetSymbolAddress((void**)&pW2,  g_W216);
    cudaGetSymbolAddress((void**)&pQ,   g_Q16);
    cudaGetSymbolAddress((void**)&pK,   g_K16);
    cudaGetSymbolAddress((void**)&pV,   g_V16);
    cudaGetSymbolAddress((void**)&pCtx, g_ctx);
    cudaGetSymbolAddress((void**)&pH16, g_h16);
    cudaGetSymbolAddress((void**)&pMid, g_mid);

    dim3 blk(256);

    // fp32 -> fp16 conversions
    cvt16_kernel<<<(M_ROWS * D_MODEL) / 1024, blk>>>(x,  pX16, M_ROWS * D_MODEL);
    cvt16_kernel<<<(D_MODEL * D_MODEL) / 1024, blk>>>(Wq, pWq, D_MODEL * D_MODEL);
    cvt16_kernel<<<(D_MODEL * D_MODEL) / 1024, blk>>>(Wk, pWk, D_MODEL * D_MODEL);
    cvt16_kernel<<<(D_MODEL * D_MODEL) / 1024, blk>>>(Wv, pWv, D_MODEL * D_MODEL);
    cvt16_kernel<<<(D_MODEL * D_MODEL) / 1024, blk>>>(Wo, pWo, D_MODEL * D_MODEL);
    cvt16_kernel<<<(D_MODEL * D_FF) / 1024, blk>>>(W1, pW1, D_MODEL * D_FF);
    cvt16_kernel<<<(D_FF * D_MODEL) / 1024, blk>>>(W2, pW2, D_FF * D_MODEL);

    dim3 gProj(D_MODEL / 128, M_ROWS / 128);   // (8, 64)
    dim3 gFF1 (D_FF   / 128, M_ROWS / 128);    // (32, 64)
    dim3 gFF2 (D_MODEL / 128, M_ROWS / 128);
    dim3 gAttn(SEQ / ATT_QT, N_HEADS, BATCH);  // (16, 16, 4)

    // QKV projections (fp16 out)
    gemm_f16_kernel<<<gProj, blk>>>(pX16, pWq, bq, pQ, D_MODEL, D_MODEL, 0, 1);
    gemm_f16_kernel<<<gProj, blk>>>(pX16, pWk, bk, pK, D_MODEL, D_MODEL, 0, 1);
    gemm_f16_kernel<<<gProj, blk>>>(pX16, pWv, bv, pV, D_MODEL, D_MODEL, 0, 1);

    // attention (fp16 in/out, fp32 softmax)
    attn_f16_kernel<<<gAttn, blk>>>(pQ, pK, pV, pCtx);

    // output projection (fp32 out for LN)
    gemm_f16_kernel<<<gProj, blk>>>(pCtx, pWo, bo, pPrj, D_MODEL, D_MODEL, 0, 0);

    // residual + LN1 (fp32 h + fp16 h16)
    add_ln_kernel<<<M_ROWS, blk>>>(pPrj, x, ln1_g, ln1_b, pH, pH16, 1);

    // FFN
    gemm_f16_kernel<<<gFF1, blk>>>(pH16, pW1, b1, pMid, D_FF, D_MODEL, 1, 1);
    gemm_f16_kernel<<<gFF2, blk>>>(pMid, pW2, b2, pF, D_MODEL, D_FF, 0, 0);

    // residual + LN2 -> output (fp32)
    add_ln_kernel<<<M_ROWS, blk>>>(pF, pH, ln2_g, ln2_b, out, pH16, 0);
}

// round 10
// speedup vs baseline: 2.3229x; 1.0113x over previous
#include <cuda_runtime.h>
#include <cuda_bf16.h>
#include <cuda_fp16.h>
#include <cstdint>
#include <stdint.h>
#include <math.h>

// ---------------------------------------------------------------------------
// Transformer encoder block, fp16 tensor-core path (m16n8k16 mma, fp32 accum).
// Attention K/V double-buffered via cp.async, single barrier per tile.
// B=4, S=2048, D=1024, H=16, d_k=64, FFN=4096
// ---------------------------------------------------------------------------

#define D_MODEL 1024
#define N_HEADS 16
#define D_K     64
#define D_FF    4096
#define SEQ     2048
#define BATCH   4
#define M_ROWS  (BATCH * SEQ)          // 8192

// fp32 scratch
__device__ float g_prj[M_ROWS * D_MODEL];
__device__ float g_h  [M_ROWS * D_MODEL];
__device__ float g_f  [M_ROWS * D_MODEL];
// fp16 scratch
__device__ __half g_x16 [M_ROWS * D_MODEL];
__device__ __half g_Wq16[D_MODEL * D_MODEL];
__device__ __half g_Wk16[D_MODEL * D_MODEL];
__device__ __half g_Wv16[D_MODEL * D_MODEL];
__device__ __half g_Wo16[D_MODEL * D_MODEL];
__device__ __half g_W116[D_MODEL * D_FF];
__device__ __half g_W216[D_FF * D_MODEL];
__device__ __half g_Q16 [M_ROWS * D_MODEL];
__device__ __half g_K16 [M_ROWS * D_MODEL];
__device__ __half g_V16 [M_ROWS * D_MODEL];
__device__ __half g_ctx [M_ROWS * D_MODEL];
__device__ __half g_h16 [M_ROWS * D_MODEL];
__device__ __half g_mid [(size_t)M_ROWS * D_FF];

// ---------------------------------------------------------------------------
// primitives
// ---------------------------------------------------------------------------
__device__ __forceinline__ void cp16(uint32_t s, const void* g) {
    asm volatile("cp.async.cg.shared.global [%0], [%1], 16;\n" :: "r"(s), "l"(g));
}
__device__ __forceinline__ void cp_commit() {
    asm volatile("cp.async.commit_group;\n" ::: "memory");
}
__device__ __forceinline__ void cp_wait_all() {
    asm volatile("cp.async.wait_group 0;\n" ::: "memory");
}

__device__ __forceinline__ void mma_f16(
    float& c0, float& c1, float& c2, float& c3,
    uint32_t a0, uint32_t a1, uint32_t a2, uint32_t a3,
    uint32_t b0, uint32_t b1)
{
    asm volatile(
        "mma.sync.aligned.m16n8k16.row.col.f32.f16.f16.f32 "
        "{%0,%1,%2,%3}, {%4,%5,%6,%7}, {%8,%9}, {%0,%1,%2,%3};\n"
        : "+f"(c0), "+f"(c1), "+f"(c2), "+f"(c3)
        : "r"(a0), "r"(a1), "r"(a2), "r"(a3), "r"(b0), "r"(b1));
}

__device__ __forceinline__ void ldsm_x4(uint32_t& r0, uint32_t& r1,
                                        uint32_t& r2, uint32_t& r3, uint32_t a) {
    asm volatile("ldmatrix.sync.aligned.m8n8.x4.shared.b16 {%0,%1,%2,%3}, [%4];"
                 : "=r"(r0), "=r"(r1), "=r"(r2), "=r"(r3) : "r"(a));
}
__device__ __forceinline__ void ldsm_x2(uint32_t& r0, uint32_t& r1, uint32_t a) {
    asm volatile("ldmatrix.sync.aligned.m8n8.x2.shared.b16 {%0,%1}, [%2];"
                 : "=r"(r0), "=r"(r1) : "r"(a));
}
__device__ __forceinline__ void ldsm_x2_t(uint32_t& r0, uint32_t& r1, uint32_t a) {
    asm volatile("ldmatrix.sync.aligned.m8n8.x2.trans.shared.b16 {%0,%1}, [%2];"
                 : "=r"(r0), "=r"(r1) : "r"(a));
}

// ---------------------------------------------------------------------------
// fp32 -> fp16 conversion (weights + x), once per launch
// ---------------------------------------------------------------------------
__global__ __launch_bounds__(256) void cvt16_kernel(
    const float* __restrict__ s, __half* __restrict__ d, int n)
{
    int i = (blockIdx.x * 256 + threadIdx.x) * 4;
    if (i < n) {
        float4 v = *(const float4*)(s + i);
        *(__half2*)(d + i)     = __floats2half2_rn(v.x, v.y);
        *(__half2*)(d + i + 2) = __floats2half2_rn(v.z, v.w);
    }
}

// ---------------------------------------------------------------------------
// FP16 GEMM: C[M,N] = A[M,K] @ B[K,N] + bias (+ReLU) (C fp32 or fp16)
// BM=128, BN=128, BK=32, 256 threads (8 warps), warp tile 64x32,
// mma m16n8k16, ldmatrix fragments, cp.async double-buffered.
// ---------------------------------------------------------------------------
#define A_STR 40
#define B_STR 136
#define A_ELE (128 * A_STR)   // 5120 halfs
#define B_ELE (32  * B_STR)   // 4352 halfs

__global__ __launch_bounds__(256) void gemm_f16_kernel(
    const __half* __restrict__ A, const __half* __restrict__ B,
    const float* __restrict__ bias, void* __restrict__ Cout,
    int N, int K, int relu, int half_out)
{
    __shared__ __half Asb[2][A_ELE];
    __shared__ __half Bsb[2][B_ELE];

    const int tid  = threadIdx.x;
    const int lane = tid & 31;
    const int warp = tid >> 5;
    const int wm   = (warp >> 2) * 64;
    const int wn   = (warp & 3) * 32;
    const int r    = lane >> 2;
    const int c    = lane & 3;
    const int bm   = blockIdx.y;
    const int bn   = blockIdx.x;

    const __half* Ab = A + (size_t)bm * 128 * K;
    const __half* Bb = B + (size_t)bn * 128;

    uint32_t asAddr[2], bsAddr[2];
    asAddr[0] = (uint32_t)__cvta_generic_to_shared(Asb[0]);
    asAddr[1] = (uint32_t)__cvta_generic_to_shared(Asb[1]);
    bsAddr[0] = (uint32_t)__cvta_generic_to_shared(Bsb[0]);
    bsAddr[1] = (uint32_t)__cvta_generic_to_shared(Bsb[1]);

    float acc[4][4][4];
    #pragma unroll
    for (int i = 0; i < 4; i++)
        #pragma unroll
        for (int j = 0; j < 4; j++)
            #pragma unroll
            for (int k = 0; k < 4; k++) acc[i][j][k] = 0.0f;

    const int KT = K / 32;

    auto issue = [&](int kk, int b) {
        #pragma unroll
        for (int i = 0; i < 2; i++) {
            int id = tid + i * 256;
            int ar = id >> 2, ac = (id & 3) * 8;
            cp16(asAddr[b] + (uint32_t)(ar * A_STR + ac) * 2,
                 Ab + (size_t)ar * K + kk + ac);
            int br = id >> 4, bc = (id & 15) * 8;
            cp16(bsAddr[b] + (uint32_t)(br * B_STR + bc) * 2,
                 Bb + (size_t)(kk + br) * N + bc);
        }
        cp_commit();
    };

    issue(0, 0);
    int buf = 0;

    const int lrow = lane & 15;
    const int lcol = (lane & 16) ? 8 : 0;

    for (int kt = 0; kt < KT; kt++) {
        if (kt + 1 < KT) {
            issue((kt + 1) * 32, buf ^ 1);
            asm volatile("cp.async.wait_group 1;\n" ::: "memory");
        } else {
            asm volatile("cp.async.wait_group 0;\n" ::: "memory");
        }
        __syncthreads();

        #pragma unroll
        for (int ks = 0; ks < 2; ks++) {
            const int k0 = ks * 16;
            uint32_t af[4][4], bf[4][2];
            #pragma unroll
            for (int ma = 0; ma < 4; ma++) {
                uint32_t a = asAddr[buf] +
                    (uint32_t)((wm + ma * 16 + lrow) * A_STR + k0 + lcol) * 2;
                ldsm_x4(af[ma][0], af[ma][1], af[ma][2], af[ma][3], a);
            }
            #pragma unroll
            for (int na = 0; na < 4; na++) {
                uint32_t a = bsAddr[buf] +
                    (uint32_t)((k0 + lrow) * B_STR + wn + na * 8) * 2;
                ldsm_x2_t(bf[na][0], bf[na][1], a);
            }
            #pragma unroll
            for (int ma = 0; ma < 4; ma++)
                #pragma unroll
                for (int na = 0; na < 4; na++)
                    mma_f16(acc[ma][na][0], acc[ma][na][1],
                            acc[ma][na][2], acc[ma][na][3],
                            af[ma][0], af[ma][1], af[ma][2], af[ma][3],
                            bf[na][0], bf[na][1]);
        }
        __syncthreads();
        buf ^= 1;
    }

    #pragma unroll
    for (int ma = 0; ma < 4; ma++) {
        const int row0 = bm * 128 + wm + ma * 16 + r;
        #pragma unroll
        for (int na = 0; na < 4; na++) {
            const int col = bn * 128 + wn + na * 8 + 2 * c;
            const float bv0 = bias[col];
            const float bv1 = bias[col + 1];
            float v0 = acc[ma][na][0] + bv0;
            float v1 = acc[ma][na][1] + bv1;
            float v2 = acc[ma][na][2] + bv0;
            float v3 = acc[ma][na][3] + bv1;
            if (relu) {
                v0 = fmaxf(v0, 0.f); v1 = fmaxf(v1, 0.f);
                v2 = fmaxf(v2, 0.f); v3 = fmaxf(v3, 0.f);
            }
            if (half_out) {
                __half* C = (__half*)Cout;
                *(__half2*)(C + (size_t)row0 * N + col)       = __floats2half2_rn(v0, v1);
                *(__half2*)(C + (size_t)(row0 + 8) * N + col) = __floats2half2_rn(v2, v3);
            } else {
                float* C = (float*)Cout;
                *(float2*)(C + (size_t)row0 * N + col)       = make_float2(v0, v1);
                *(float2*)(C + (size_t)(row0 + 8) * N + col) = make_float2(v2, v3);
            }
        }
    }
}

// ---------------------------------------------------------------------------
// Flash attention, fp16 mma, fp32 softmax. cp.async double-buffered K/V,
// single __syncthreads per k-tile.
// Block: 128 q-rows, 256 threads (8 warps x 16 rows). K/V tile: 64 keys.
// Smem (halfs, stride 72): Ks[2][64][72], Vs[2][64][72], Ps[128][72]
// P/Q rows in Ps are strictly warp-private -> __syncwarp suffices mid-tile.
// ---------------------------------------------------------------------------
#define ATT_QT  128
#define ATT_KT  64
#define AKS_STR 72
#define KV_ELE  (ATT_KT * AKS_STR)            // 4608 halfs
#define PS_ELE  (ATT_QT * AKS_STR)            // 9216 halfs
#define ATT_SMEM_BYTES ((4 * KV_ELE + PS_ELE) * 2)   // 55296

__global__ __launch_bounds__(256, 2) void attn_f16_kernel(
    const __half* __restrict__ Q, const __half* __restrict__ K,
    const __half* __restrict__ V, __half* __restrict__ O)
{
    extern __shared__ __half smh[];
    __half* Ksb[2] = { smh,              smh + KV_ELE };
    __half* Vsb[2] = { smh + 2 * KV_ELE, smh + 3 * KV_ELE };
    __half* Ps     = smh + 4 * KV_ELE;

    const int b    = blockIdx.z;
    const int h    = blockIdx.y;
    const int qt   = blockIdx.x;
    const int tid  = threadIdx.x;
    const int lane = tid & 31;
    const int warp = tid >> 5;
    const int r    = lane >> 2;       // 0..7
    const int c    = lane & 3;        // 0..3
    const int wm   = warp * 16;
    const int lrow = lane & 15;
    const int lcol = (lane & 16) ? 8 : 0;

    const size_t qrow0 = (size_t)b * SEQ + (size_t)qt * ATT_QT;
    const __half* Qb = Q + qrow0 * D_MODEL + h * D_K;
    const __half* Kb = K + (size_t)b * SEQ * D_MODEL + h * D_K;
    const __half* Vb = V + (size_t)b * SEQ * D_MODEL + h * D_K;

    uint32_t ksA[2], vsA[2];
    ksA[0] = (uint32_t)__cvta_generic_to_shared(Ksb[0]);
    ksA[1] = (uint32_t)__cvta_generic_to_shared(Ksb[1]);
    vsA[0] = (uint32_t)__cvta_generic_to_shared(Vsb[0]);
    vsA[1] = (uint32_t)__cvta_generic_to_shared(Vsb[1]);
    const uint32_t psB = (uint32_t)__cvta_generic_to_shared(Ps);

    auto issue_kv = [&](int kt, int buf) {
        #pragma unroll
        for (int i = 0; i < 2; i++) {
            int id  = tid + i * 256;            // 512 chunks of 8 halfs each
            int row = id >> 3, c8 = (id & 7) * 8;
            const size_t gro = (size_t)(kt * ATT_KT + row) * D_MODEL + c8;
            cp16(ksA[buf] + (uint32_t)(row * AKS_STR + c8) * 2, Kb + gro);
            cp16(vsA[buf] + (uint32_t)(row * AKS_STR + c8) * 2, Vb + gro);
        }
        cp_commit();
    };

    // prefetch tile 0 while staging Q
    issue_kv(0, 0);

    // stage Q tile (128 x 64 halfs) into Ps, load Q fragments to regs
    #pragma unroll
    for (int i = 0; i < 4; i++) {
        int id = tid + i * 256;
        int row = id >> 3, c8 = (id & 7) * 8;
        *(uint4*)&Ps[row * AKS_STR + c8] =
            *(const uint4*)(Qb + (size_t)row * D_MODEL + c8);
    }
    __syncthreads();

    uint32_t qa[4][4];
    #pragma unroll
    for (int ks = 0; ks < 4; ks++) {
        uint32_t a = psB + (uint32_t)((wm + lrow) * AKS_STR + ks * 16 + lcol) * 2;
        ldsm_x4(qa[ks][0], qa[ks][1], qa[ks][2], qa[ks][3], a);
    }
    // Ps rows wm..wm+15 are read/written only by this warp; no block sync needed

    float oacc[8][4];
    #pragma unroll
    for (int nt = 0; nt < 8; nt++)
        #pragma unroll
        for (int i = 0; i < 4; i++) oacc[nt][i] = 0.0f;

    float m0 = -1e30f, m1 = -1e30f, l0 = 0.0f, l1 = 0.0f;

    const int NT = SEQ / ATT_KT;
    for (int kt = 0; kt < NT; kt++) {
        cp_wait_all();
        __syncthreads();                 // tile kt visible; all warps done with kt-1
        if (kt + 1 < NT) issue_kv(kt + 1, (kt + 1) & 1);

        const uint32_t ksBuf = ksA[kt & 1];
        const uint32_t vsBuf = vsA[kt & 1];

        // ---- S = Q @ K^T
        float sacc[8][4];
        #pragma unroll
        for (int nt = 0; nt < 8; nt++) {
            sacc[nt][0] = sacc[nt][1] = sacc[nt][2] = sacc[nt][3] = 0.0f;
            #pragma unroll
            for (int ks = 0; ks < 4; ks++) {
                uint32_t addr = ksBuf + (uint32_t)(
                    (nt * 8 + (lane & 7)) * AKS_STR + ks * 16 + ((lane & 8) ? 8 : 0)) * 2;
                uint32_t b0, b1;
                ldsm_x2(b0, b1, addr);
                mma_f16(sacc[nt][0], sacc[nt][1], sacc[nt][2], sacc[nt][3],
                        qa[ks][0], qa[ks][1], qa[ks][2], qa[ks][3], b0, b1);
            }
            sacc[nt][0] *= 0.125f; sacc[nt][1] *= 0.125f;
            sacc[nt][2] *= 0.125f; sacc[nt][3] *= 0.125f;
        }

        // ---- online softmax (thread owns rows wm+r, wm+r+8)
        float tm0 = -1e30f, tm1 = -1e30f;
        #pragma unroll
        for (int nt = 0; nt < 8; nt++) {
            tm0 = fmaxf(tm0, fmaxf(sacc[nt][0], sacc[nt][1]));
            tm1 = fmaxf(tm1, fmaxf(sacc[nt][2], sacc[nt][3]));
        }
        tm0 = fmaxf(tm0, __shfl_xor_sync(0xffffffffu, tm0, 1));
        tm0 = fmaxf(tm0, __shfl_xor_sync(0xffffffffu, tm0, 2));
        tm1 = fmaxf(tm1, __shfl_xor_sync(0xffffffffu, tm1, 1));
        tm1 = fmaxf(tm1, __shfl_xor_sync(0xffffffffu, tm1, 2));

        const float mn0 = fmaxf(m0, tm0);
        const float mn1 = fmaxf(m1, tm1);
        const float fac0 = __expf(m0 - mn0);
        const float fac1 = __expf(m1 - mn1);
        m0 = mn0; m1 = mn1;

        float ts0 = 0.0f, ts1 = 0.0f;
        #pragma unroll
        for (int nt = 0; nt < 8; nt++) {
            float p0 = __expf(sacc[nt][0] - mn0);
            float p1 = __expf(sacc[nt][1] - mn0);
            float p2 = __expf(sacc[nt][2] - mn1);
            float p3 = __expf(sacc[nt][3] - mn1);
            ts0 += p0 + p1;
            ts1 += p2 + p3;
            const int col = nt * 8 + c * 2;
            *(__half2*)&Ps[(wm + r) * AKS_STR + col]     = __floats2half2_rn(p0, p1);
            *(__half2*)&Ps[(wm + r + 8) * AKS_STR + col] = __floats2half2_rn(p2, p3);
        }
        ts0 += __shfl_xor_sync(0xffffffffu, ts0, 1);
        ts0 += __shfl_xor_sync(0xffffffffu, ts0, 2);
        ts1 += __shfl_xor_sync(0xffffffffu, ts1, 1);
        ts1 += __shfl_xor_sync(0xffffffffu, ts1, 2);
        l0 = l0 * fac0 + ts0;
        l1 = l1 * fac1 + ts1;

        #pragma unroll
        for (int nt = 0; nt < 8; nt++) {
            oacc[nt][0] *= fac0; oacc[nt][1] *= fac0;
            oacc[nt][2] *= fac1; oacc[nt][3] *= fac1;
        }

        __syncwarp();   // P stripe is warp-private

        // ---- O += P @ V
        #pragma unroll
        for (int ks = 0; ks < 4; ks++) {
            const int k0 = ks * 16;
            uint32_t a0, a1, a2, a3;
            ldsm_x4(a0, a1, a2, a3,
                    psB + (uint32_t)((wm + lrow) * AKS_STR + k0 + lcol) * 2);
            #pragma unroll
            for (int nt = 0; nt < 8; nt++) {
                uint32_t b0, b1;
                ldsm_x2_t(b0, b1,
                          vsBuf + (uint32_t)((k0 + lrow) * AKS_STR + nt * 8) * 2);
                mma_f16(oacc[nt][0], oacc[nt][1], oacc[nt][2], oacc[nt][3],
                        a0, a1, a2, a3, b0, b1);
            }
        }
    }

    // ---- normalize and store (fp16 ctx)
    const float inv0 = 1.0f / l0;
    const float inv1 = 1.0f / l1;
    __half* Ob = O + qrow0 * D_MODEL + h * D_K;
    #pragma unroll
    for (int nt = 0; nt < 8; nt++) {
        const int col = nt * 8 + c * 2;
        *(__half2*)(Ob + (size_t)(wm + r) * D_MODEL + col) =
            __floats2half2_rn(oacc[nt][0] * inv0, oacc[nt][1] * inv0);
        *(__half2*)(Ob + (size_t)(wm + r + 8) * D_MODEL + col) =
            __floats2half2_rn(oacc[nt][2] * inv1, oacc[nt][3] * inv1);
    }
}

// ---------------------------------------------------------------------------
// Fused residual-add + LayerNorm: out = LN(a + b) * g + beta (+fp16 copy)
// ---------------------------------------------------------------------------
__global__ __launch_bounds__(256) void add_ln_kernel(
    const float* __restrict__ a, const float* __restrict__ b,
    const float* __restrict__ g, const float* __restrict__ beta,
    float* __restrict__ out, __half* __restrict__ out16, int w16)
{
    const int row = blockIdx.x;
    const int tid = threadIdx.x;

    const float4 av = *(const float4*)(a + (size_t)row * D_MODEL + tid * 4);
    const float4 bv = *(const float4*)(b + (size_t)row * D_MODEL + tid * 4);
    float4 v;
    v.x = av.x + bv.x; v.y = av.y + bv.y; v.z = av.z + bv.z; v.w = av.w + bv.w;

    float s  = v.x + v.y + v.z + v.w;
    float sq = v.x * v.x + v.y * v.y + v.z * v.z + v.w * v.w;

    #pragma unroll
    for (int off = 16; off; off >>= 1) {
        s  += __shfl_xor_sync(0xffffffffu, s,  off);
        sq += __shfl_xor_sync(0xffffffffu, sq, off);
    }
    __shared__ float red_s[8], red_q[8];
    if ((tid & 31) == 0) { red_s[tid >> 5] = s; red_q[tid >> 5] = sq; }
    __syncthreads();
    __shared__ float smean, srstd;
    if (tid == 0) {
        float ts = 0.f, tq = 0.f;
        #pragma unroll
        for (int i = 0; i < 8; i++) { ts += red_s[i]; tq += red_q[i]; }
        float mean = ts * (1.0f / D_MODEL);
        float var  = tq * (1.0f / D_MODEL) - mean * mean;
        smean = mean;
        srstd = rsqrtf(var + 1e-5f);
    }
    __syncthreads();
    const float mean = smean, rstd = srstd;

    const float4 gv = *(const float4*)(g    + tid * 4);
    const float4 tv = *(const float4*)(beta + tid * 4);
    float4 o;
    o.x = (v.x - mean) * rstd * gv.x + tv.x;
    o.y = (v.y - mean) * rstd * gv.y + tv.y;
    o.z = (v.z - mean) * rstd * gv.z + tv.z;
    o.w = (v.w - mean) * rstd * gv.w + tv.w;
    *(float4*)(out + (size_t)row * D_MODEL + tid * 4) = o;
    if (w16) {
        *(__half2*)(out16 + (size_t)row * D_MODEL + tid * 4)     = __floats2half2_rn(o.x, o.y);
        *(__half2*)(out16 + (size_t)row * D_MODEL + tid * 4 + 2) = __floats2half2_rn(o.z, o.w);
    }
}

// ---------------------------------------------------------------------------
// Launch
// ---------------------------------------------------------------------------
extern "C" void kernel_launch(void* const* d_in, const int* in_sizes, int n_in,
                              void* d_out, int out_size)
{
    const float* x     = (const float*)d_in[0];
    const float* Wq    = (const float*)d_in[1];
    const float* bq    = (const float*)d_in[2];
    const float* Wk    = (const float*)d_in[3];
    const float* bk    = (const float*)d_in[4];
    const float* Wv    = (const float*)d_in[5];
    const float* bv    = (const float*)d_in[6];
    const float* Wo    = (const float*)d_in[7];
    const float* bo    = (const float*)d_in[8];
    const float* ln1_g = (const float*)d_in[9];
    const float* ln1_b = (const float*)d_in[10];
    const float* W1    = (const float*)d_in[11];
    const float* b1    = (const float*)d_in[12];
    const float* W2    = (const float*)d_in[13];
    const float* b2    = (const float*)d_in[14];
    const float* ln2_g = (const float*)d_in[15];
    const float* ln2_b = (const float*)d_in[16];
    float* out = (float*)d_out;

    float *pPrj, *pH, *pF;
    __half *pX16, *pWq, *pWk, *pWv, *pWo, *pW1, *pW2;
    __half *pQ, *pK, *pV, *pCtx, *pH16, *pMid;
    cudaGetSymbolAddress((void**)&pPrj, g_prj);
    cudaGetSymbolAddress((void**)&pH,   g_h);
    cudaGetSymbolAddress((void**)&pF,   g_f);
    cudaGetSymbolAddress((void**)&pX16, g_x16);
    cudaGetSymbolAddress((void**)&pWq,  g_Wq16);
    cudaGetSymbolAddress((void**)&pWk,  g_Wk16);
    cudaGetSymbolAddress((void**)&pWv,  g_Wv16);
    cudaGetSymbolAddress((void**)&pWo,  g_Wo16);
    cudaGetSymbolAddress((void**)&pW1,  g_W116);
    cudaGetSymbolAddress((void**)&pW2,  g_W216);
    cudaGetSymbolAddress((void**)&pQ,   g_Q16);
    cudaGetSymbolAddress((void**)&pK,   g_K16);
    cudaGetSymbolAddress((void**)&pV,   g_V16);
    cudaGetSymbolAddress((void**)&pCtx, g_ctx);
    cudaGetSymbolAddress((void**)&pH16, g_h16);
    cudaGetSymbolAddress((void**)&pMid, g_mid);

    cudaFuncSetAttribute(attn_f16_kernel,
                         cudaFuncAttributeMaxDynamicSharedMemorySize,
                         ATT_SMEM_BYTES);

    dim3 blk(256);

    // fp32 -> fp16 conversions
    cvt16_kernel<<<(M_ROWS * D_MODEL) / 1024, blk>>>(x,  pX16, M_ROWS * D_MODEL);
    cvt16_kernel<<<(D_MODEL * D_MODEL) / 1024, blk>>>(Wq, pWq, D_MODEL * D_MODEL);
    cvt16_kernel<<<(D_MODEL * D_MODEL) / 1024, blk>>>(Wk, pWk, D_MODEL * D_MODEL);
    cvt16_kernel<<<(D_MODEL * D_MODEL) / 1024, blk>>>(Wv, pWv, D_MODEL * D_MODEL);
    cvt16_kernel<<<(D_MODEL * D_MODEL) / 1024, blk>>>(Wo, pWo, D_MODEL * D_MODEL);
    cvt16_kernel<<<(D_MODEL * D_FF) / 1024, blk>>>(W1, pW1, D_MODEL * D_FF);
    cvt16_kernel<<<(D_FF * D_MODEL) / 1024, blk>>>(W2, pW2, D_FF * D_MODEL);

    dim3 gProj(D_MODEL / 128, M_ROWS / 128);   // (8, 64)
    dim3 gFF1 (D_FF   / 128, M_ROWS / 128);    // (32, 64)
    dim3 gFF2 (D_MODEL / 128, M_ROWS / 128);
    dim3 gAttn(SEQ / ATT_QT, N_HEADS, BATCH);  // (16, 16, 4)

    // QKV projections (fp16 out)
    gemm_f16_kernel<<<gProj, blk>>>(pX16, pWq, bq, pQ, D_MODEL, D_MODEL, 0, 1);
    gemm_f16_kernel<<<gProj, blk>>>(pX16, pWk, bk, pK, D_MODEL, D_MODEL, 0, 1);
    gemm_f16_kernel<<<gProj, blk>>>(pX16, pWv, bv, pV, D_MODEL, D_MODEL, 0, 1);

    // attention (fp16, double-buffered)
    attn_f16_kernel<<<gAttn, blk, ATT_SMEM_BYTES>>>(pQ, pK, pV, pCtx);

    // output projection (fp32 out for LN)
    gemm_f16_kernel<<<gProj, blk>>>(pCtx, pWo, bo, pPrj, D_MODEL, D_MODEL, 0, 0);

    // residual + LN1 (fp32 h + fp16 h16)
    add_ln_kernel<<<M_ROWS, blk>>>(pPrj, x, ln1_g, ln1_b, pH, pH16, 1);

    // FFN
    gemm_f16_kernel<<<gFF1, blk>>>(pH16, pW1, b1, pMid, D_FF, D_MODEL, 1, 1);
    gemm_f16_kernel<<<gFF2, blk>>>(pMid, pW2, b2, pF, D_MODEL, D_FF, 0, 0);

    // residual + LN2 -> output (fp32)
    add_ln_kernel<<<M_ROWS, blk>>>(pF, pH, ln2_g, ln2_b, out, pH16, 0);
}